// round 13
// baseline (speedup 1.0000x reference)
#include <cuda_runtime.h>
#include <cuda_fp16.h>
#include <cstdint>

// ============================================================================
// Problem constants
// ============================================================================
#define N_ATOMS   32768
#define N_SPECIES 4
#define N_FEAT    7584
#define N_FEAT_P  7616      // padded to multiple of KC
#define HIDDEN    256

#define MT       128        // CTA rows
#define NT       256        // CTA cols (full hidden width)
#define KC       64         // k-chunk per stage
#define NTHREADS 512        // 16 warps, 32x64 warp tiles
#define TOTCH    (N_FEAT_P / KC)   // 119
#define NCHS     30                // split-K chunks/slice (30,30,30,29)
#define NSPLIT   4

// smem: rows of 64 fp16 = 128B data + 16B pad -> conflict-free ldmatrix
#define RST      144
#define APLANE   (128 * RST)           // 18432
#define BPLANE   (256 * RST)           // 36864
#define SOFF_AH  0
#define SOFF_AL  (APLANE)
#define SOFF_BH  (2 * APLANE)
#define STAGE    (2 * APLANE + BPLANE) // 73728
#define NSTAGE   3
#define OFF_BIAS (NSTAGE * STAGE)      // 221184
#define SMEM_DYN (OFF_BIAS + 1024)     // 222208 (< 227KB limit)

// ============================================================================
// Device scratch (allocation-free)
// ============================================================================
__device__ __align__(16) __half g_W1h[(size_t)N_SPECIES * HIDDEN * N_FEAT_P];
__device__ __align__(16) __half g_W2h[N_SPECIES * HIDDEN * HIDDEN];
__device__ __align__(16) __half g_W3h[N_SPECIES * HIDDEN * HIDDEN];
__device__ __align__(16) __half g_H1h[(size_t)N_ATOMS * HIDDEN];
__device__ __align__(16) __half g_H1l[(size_t)N_ATOMS * HIDDEN];
__device__ __align__(16) __half g_H2h[(size_t)N_ATOMS * HIDDEN];
__device__ __align__(16) __half g_H2l[(size_t)N_ATOMS * HIDDEN];
__device__ __align__(16) float  g_P[(size_t)NSPLIT * N_ATOMS * HIDDEN];

// ============================================================================
// Baseline-PTX primitives
// ============================================================================
__device__ __forceinline__ void cp16(uint32_t s, const void* g) {
    asm volatile("cp.async.cg.shared.global [%0], [%1], 16;\n" :: "r"(s), "l"(g));
}
__device__ __forceinline__ void cp_commit() {
    asm volatile("cp.async.commit_group;\n" ::: "memory");
}
template<int N> __device__ __forceinline__ void cp_wait() {
    asm volatile("cp.async.wait_group %0;\n" :: "n"(N) : "memory");
}
__device__ __forceinline__ void ldsm4(uint32_t& r0, uint32_t& r1, uint32_t& r2,
                                      uint32_t& r3, uint32_t a) {
    asm volatile("ldmatrix.sync.aligned.m8n8.x4.shared.b16 {%0,%1,%2,%3}, [%4];\n"
                 : "=r"(r0), "=r"(r1), "=r"(r2), "=r"(r3) : "r"(a));
}
__device__ __forceinline__ void mmaf16(float* c, const uint32_t* a, const uint32_t* b) {
    asm volatile(
        "mma.sync.aligned.m16n8k16.row.col.f32.f16.f16.f32 "
        "{%0,%1,%2,%3}, {%4,%5,%6,%7}, {%8,%9}, {%0,%1,%2,%3};\n"
        : "+f"(c[0]), "+f"(c[1]), "+f"(c[2]), "+f"(c[3])
        : "r"(a[0]), "r"(a[1]), "r"(a[2]), "r"(a[3]), "r"(b[0]), "r"(b[1]));
}
__device__ __forceinline__ uint32_t pkh(__half a, __half b) {
    __half2 t; t.x = a; t.y = b;
    return *(uint32_t*)&t;
}

// Fragment set for one k16 step (32x64 warp tile, 2-term)
struct Frag {
    uint32_t ah[2][4], al[2][4];   // A: 2 m16 tiles, hi/lo planes
    uint32_t bh[8][2];             // B: 8 n8 tiles, hi plane only
};

// ============================================================================
// Stage loaders (512 threads, KC=64)
// ============================================================================
// B hi plane: 256 rows x 8 segs = 2048 cp16 -> 4/thread
__device__ __forceinline__ void cp_B(uint32_t st, const __half* B0, int ldb, int k0,
                                     int tid) {
#pragma unroll
    for (int i = 0; i < 4; ++i) {
        int j = tid + i * NTHREADS;
        int n = j >> 3, seg = j & 7;
        cp16(st + SOFF_BH + n * RST + seg * 16, B0 + (size_t)n * ldb + k0 + seg * 8);
    }
}
// A hi/lo planes via cp (layers 2/3)
__device__ __forceinline__ void cp_A(uint32_t st, const __half* Ah0, const __half* Al0,
                                     int k0, int tid) {
#pragma unroll
    for (int i = 0; i < 2; ++i) {
        int j = tid + i * NTHREADS;
        int m = j >> 3, seg = j & 7;
        cp16(st + SOFF_AH + m * RST + seg * 16, Ah0 + (size_t)m * HIDDEN + k0 + seg * 8);
        cp16(st + SOFF_AL + m * RST + seg * 16, Al0 + (size_t)m * HIDDEN + k0 + seg * 8);
    }
}
// A fp32 (features): 128 rows x 16 quads = 2048 float4 -> halves of 2/thread
template<int H>
__device__ __forceinline__ void ldg_A_half(float4 av[2], const float* Abase, int k0,
                                           int tid, int Klim) {
#pragma unroll
    for (int i = 0; i < 2; ++i) {
        int j = tid + (H * 2 + i) * NTHREADS;
        int r = j >> 4, q = j & 15;
        int kg = k0 + q * 4;
        if (kg < Klim) av[i] = *(const float4*)(Abase + (size_t)r * N_FEAT + kg);
        else           av[i] = make_float4(0.f, 0.f, 0.f, 0.f);
    }
}
template<int H>
__device__ __forceinline__ void sts_A_half(const float4 av[2], char* sm, uint32_t stOff,
                                           int tid) {
#pragma unroll
    for (int i = 0; i < 2; ++i) {
        int j = tid + (H * 2 + i) * NTHREADS;
        int r = j >> 4, q = j & 15;
        float4 x = av[i];
        __half h0 = __float2half_rn(x.x), h1 = __float2half_rn(x.y);
        __half h2 = __float2half_rn(x.z), h3 = __float2half_rn(x.w);
        uint2 hp, lp;
        hp.x = pkh(h0, h1); hp.y = pkh(h2, h3);
        lp.x = pkh(__float2half_rn(x.x - __half2float(h0)),
                   __float2half_rn(x.y - __half2float(h1)));
        lp.y = pkh(__float2half_rn(x.z - __half2float(h2)),
                   __float2half_rn(x.w - __half2float(h3)));
        *(uint2*)(sm + stOff + SOFF_AH + r * RST + q * 8) = hp;
        *(uint2*)(sm + stOff + SOFF_AL + r * RST + q * 8) = lp;
    }
}

// ============================================================================
// Fragment load + MMA (2-term)
// ============================================================================
__device__ __forceinline__ void ldsm_step(uint32_t st, int ks, Frag& f,
                                          const uint32_t aOff[2], const uint32_t bOff[4]) {
#pragma unroll
    for (int mt = 0; mt < 2; ++mt) {
        ldsm4(f.ah[mt][0], f.ah[mt][1], f.ah[mt][2], f.ah[mt][3], st + aOff[mt] + ks * 32);
        ldsm4(f.al[mt][0], f.al[mt][1], f.al[mt][2], f.al[mt][3],
              st + aOff[mt] + APLANE + ks * 32);
    }
#pragma unroll
    for (int ng = 0; ng < 4; ++ng)
        ldsm4(f.bh[2 * ng][0], f.bh[2 * ng][1], f.bh[2 * ng + 1][0], f.bh[2 * ng + 1][1],
              st + bOff[ng] + ks * 32);
}
// Two passes: hi-term for all 16 accumulators, then lo-term. Same accumulator
// is reused at distance 16 instructions (was distance 1) -> no RAW stall on acc.
__device__ __forceinline__ void mma_step(float acc[2][8][4], const Frag& f) {
#pragma unroll
    for (int mt = 0; mt < 2; ++mt)
#pragma unroll
        for (int nt = 0; nt < 8; ++nt)
            mmaf16(acc[mt][nt], f.ah[mt], f.bh[nt]);
#pragma unroll
    for (int mt = 0; mt < 2; ++mt)
#pragma unroll
        for (int nt = 0; nt < 8; ++nt)
            mmaf16(acc[mt][nt], f.al[mt], f.bh[nt]);
}

// ============================================================================
// Main GEMM.  D[m,n] = sum_k A[m,k]*B[n,k]   (2-term fp16, fp32 accum)
// ============================================================================
template<bool AFP32, bool SPLIT>
__global__ void __launch_bounds__(NTHREADS, 1)
gemm_main(const float* __restrict__ Afp,
          const __half* __restrict__ Ahg, const __half* __restrict__ Alg,
          int nchS, int nchTot,
          const __half* __restrict__ Bhg, int ldb,
          const float* __restrict__ bias,
          __half* __restrict__ Oh, __half* __restrict__ Ol,
          float* __restrict__ Pout)
{
    extern __shared__ char sm[];
    const uint32_t sb = (uint32_t)__cvta_generic_to_shared(sm);
    const int tid = threadIdx.x;
    const int row0 = blockIdx.y * MT;
    const int s = row0 >> 13;
    const int z = SPLIT ? blockIdx.z : 0;
    const int kbase = z * nchS * KC;
    const int nch = SPLIT ? min(nchS, nchTot - z * nchS) : nchS;
    const int Klim = AFP32 ? (N_FEAT - kbase) : 0x7fffffff;

    const __half* Bh0 = Bhg + (size_t)s * HIDDEN * ldb + kbase;
    const float* Abase = AFP32 ? (Afp + (size_t)row0 * N_FEAT + kbase) : nullptr;
    const __half* Ah0 = AFP32 ? nullptr : (Ahg + (size_t)row0 * HIDDEN);
    const __half* Al0 = AFP32 ? nullptr : (Alg + (size_t)row0 * HIDDEN);

    float* sbias = (float*)(sm + OFF_BIAS);
    if (!SPLIT && tid < NT) sbias[tid] = bias[s * HIDDEN + tid];

    // ---- prologue: fill stages 0 and 1 ----
    float4 av[2];
    if (AFP32) {
        ldg_A_half<0>(av, Abase, 0, tid, Klim);
        sts_A_half<0>(av, sm, 0, tid);
        ldg_A_half<1>(av, Abase, 0, tid, Klim);
        sts_A_half<1>(av, sm, 0, tid);
    } else {
        cp_A(sb, Ah0, Al0, 0, tid);
    }
    cp_B(sb, Bh0, ldb, 0, tid);
    cp_commit();
    if (AFP32) {
        ldg_A_half<0>(av, Abase, KC, tid, Klim);
        sts_A_half<0>(av, sm, STAGE, tid);
        ldg_A_half<1>(av, Abase, KC, tid, Klim);
        sts_A_half<1>(av, sm, STAGE, tid);
    } else {
        cp_A(sb + STAGE, Ah0, Al0, KC, tid);
    }
    cp_B(sb + STAGE, Bh0, ldb, KC, tid);
    cp_commit();

    // ---- per-warp fragment addressing: 16 warps, 32x64 tiles (4M x 4N) ----
    const int lane = tid & 31, wid = tid >> 5;
    const int m0 = (wid & 3) * 32, n0 = (wid >> 2) * 64;
    const int lr = lane & 15, lcb = (lane >> 4) * 16;
    uint32_t aOff[2], bOff[4];
#pragma unroll
    for (int mt = 0; mt < 2; ++mt)
        aOff[mt] = SOFF_AH + (uint32_t)(m0 + mt * 16 + lr) * RST + lcb;
    const int brow = (lane & 7) + ((lane & 16) >> 1);
    const int bcb = (lane & 8) * 2;
#pragma unroll
    for (int ng = 0; ng < 4; ++ng)
        bOff[ng] = SOFF_BH + (uint32_t)(n0 + ng * 16 + brow) * RST + bcb;

    float acc[2][8][4];
#pragma unroll
    for (int mt = 0; mt < 2; ++mt)
#pragma unroll
        for (int nt = 0; nt < 8; ++nt)
#pragma unroll
            for (int q = 0; q < 4; ++q) acc[mt][nt][q] = 0.f;

    // ---- main loop: 3-stage ring, cp_wait<1>, chores spread over k-steps ----
    Frag f;
    int stc = 0, st2 = 2;
    for (int c = 0; c < nch; ++c) {
        if (c + 1 < nch) { cp_wait<1>(); } else { cp_wait<0>(); }
        __syncthreads();
        const uint32_t cur = sb + (uint32_t)stc * STAGE;
        const uint32_t nx2 = sb + (uint32_t)st2 * STAGE;
        const uint32_t nx2off = (uint32_t)st2 * STAGE;
        const bool pf = (c + 2 < nch);
        const int k2 = (c + 2) * KC;

        // ks0: + ldg half0 of A(c+2)
        ldsm_step(cur, 0, f, aOff, bOff);
        if (AFP32 && pf) ldg_A_half<0>(av, Abase, k2, tid, Klim);
        mma_step(acc, f);

        // ks1: + sts half0 -> stage c+2, cp_B(c+2)
        ldsm_step(cur, 1, f, aOff, bOff);
        if (AFP32 && pf) sts_A_half<0>(av, sm, nx2off, tid);
        if (pf) cp_B(nx2, Bh0, ldb, k2, tid);
        mma_step(acc, f);

        // ks2: + ldg half1, cp_A (layers 2/3), commit
        ldsm_step(cur, 2, f, aOff, bOff);
        if (AFP32 && pf) ldg_A_half<1>(av, Abase, k2, tid, Klim);
        if (pf) {
            if (!AFP32) cp_A(nx2, Ah0, Al0, k2, tid);
            cp_commit();
        }
        mma_step(acc, f);

        // ks3: + sts half1 -> stage c+2
        ldsm_step(cur, 3, f, aOff, bOff);
        if (AFP32 && pf) sts_A_half<1>(av, sm, nx2off, tid);
        mma_step(acc, f);

        stc = (stc == 2) ? 0 : stc + 1;
        st2 = (st2 == 2) ? 0 : st2 + 1;
    }

    // ---- epilogue ----
    if (SPLIT) {
        float* P = Pout + (size_t)z * N_ATOMS * HIDDEN;
#pragma unroll
        for (int mt = 0; mt < 2; ++mt)
#pragma unroll
            for (int nt = 0; nt < 8; ++nt) {
                const int rg = row0 + m0 + mt * 16 + (lane >> 2);
                const int cg = n0 + nt * 8 + (lane & 3) * 2;
                *(float2*)(P + (size_t)rg * HIDDEN + cg) =
                    make_float2(acc[mt][nt][0], acc[mt][nt][1]);
                *(float2*)(P + (size_t)(rg + 8) * HIDDEN + cg) =
                    make_float2(acc[mt][nt][2], acc[mt][nt][3]);
            }
    } else {
#pragma unroll
        for (int mt = 0; mt < 2; ++mt)
#pragma unroll
            for (int nt = 0; nt < 8; ++nt) {
                const int rg = row0 + m0 + mt * 16 + (lane >> 2);
                const int cg = n0 + nt * 8 + (lane & 3) * 2;
                const float b0 = sbias[cg], b1 = sbias[cg + 1];
                float v[4];
                v[0] = acc[mt][nt][0] + b0; v[1] = acc[mt][nt][1] + b1;
                v[2] = acc[mt][nt][2] + b0; v[3] = acc[mt][nt][3] + b1;
#pragma unroll
                for (int q = 0; q < 4; ++q) v[q] = v[q] / (1.f + __expf(-v[q]));
                __half h0 = __float2half_rn(v[0]), h1 = __float2half_rn(v[1]);
                __half h2 = __float2half_rn(v[2]), h3 = __float2half_rn(v[3]);
                uint32_t hi0 = pkh(h0, h1), hi1 = pkh(h2, h3);
                uint32_t lo0 = pkh(__float2half_rn(v[0] - __half2float(h0)),
                                   __float2half_rn(v[1] - __half2float(h1)));
                uint32_t lo1 = pkh(__float2half_rn(v[2] - __half2float(h2)),
                                   __float2half_rn(v[3] - __half2float(h3)));
                *(uint32_t*)(Oh + (size_t)rg * HIDDEN + cg) = hi0;
                *(uint32_t*)(Ol + (size_t)rg * HIDDEN + cg) = lo0;
                *(uint32_t*)(Oh + (size_t)(rg + 8) * HIDDEN + cg) = hi1;
                *(uint32_t*)(Ol + (size_t)(rg + 8) * HIDDEN + cg) = lo1;
            }
    }
}

// ============================================================================
// Split-K combine: sum 4 partials + bias -> silu -> fp16 hi/lo planes
// ============================================================================
__global__ void __launch_bounds__(256)
combine_silu(const float* __restrict__ P, const float* __restrict__ bias,
             __half* __restrict__ Oh, __half* __restrict__ Ol)
{
    const size_t i4 = ((size_t)blockIdx.x * 256 + threadIdx.x) * 4;
    const int row = (int)(i4 >> 8);
    const int col = (int)(i4 & 255);
    const int s = row >> 13;
    float4 a0 = *(const float4*)(P + i4);
    float4 a1 = *(const float4*)(P + (size_t)N_ATOMS * HIDDEN + i4);
    float4 a2 = *(const float4*)(P + (size_t)2 * N_ATOMS * HIDDEN + i4);
    float4 a3 = *(const float4*)(P + (size_t)3 * N_ATOMS * HIDDEN + i4);
    const float* bp = bias + s * HIDDEN + col;
    float v[4] = {(a0.x + a1.x) + (a2.x + a3.x) + bp[0],
                  (a0.y + a1.y) + (a2.y + a3.y) + bp[1],
                  (a0.z + a1.z) + (a2.z + a3.z) + bp[2],
                  (a0.w + a1.w) + (a2.w + a3.w) + bp[3]};
#pragma unroll
    for (int q = 0; q < 4; ++q) v[q] = v[q] / (1.f + __expf(-v[q]));
    __half h0 = __float2half_rn(v[0]), h1 = __float2half_rn(v[1]);
    __half h2 = __float2half_rn(v[2]), h3 = __float2half_rn(v[3]);
    uint2 hp, lp;
    hp.x = pkh(h0, h1); hp.y = pkh(h2, h3);
    lp.x = pkh(__float2half_rn(v[0] - __half2float(h0)),
               __float2half_rn(v[1] - __half2float(h1)));
    lp.y = pkh(__float2half_rn(v[2] - __half2float(h2)),
               __float2half_rn(v[3] - __half2float(h3)));
    *(uint2*)(Oh + i4) = hp;
    *(uint2*)(Ol + i4) = lp;
}

// ============================================================================
// Weight transpose to K-major fp16 (zero-padded to Fp):  W[s][f][h] -> T[s][h][fp]
// ============================================================================
__global__ void transpose_w(const float* __restrict__ W, __half* __restrict__ Th,
                            int F, int Fp, int H)
{
    __shared__ float t[32][33];
    const int s = blockIdx.z;
    const int f0 = blockIdx.x * 32, h0 = blockIdx.y * 32;
    const float* Ws = W + (size_t)s * F * H;
#pragma unroll
    for (int i = threadIdx.y; i < 32; i += 8) {
        int f = f0 + i, h = h0 + threadIdx.x;
        t[i][threadIdx.x] = (f < F) ? Ws[(size_t)f * H + h] : 0.f;
    }
    __syncthreads();
    __half* Ths = Th + (size_t)s * H * Fp;
#pragma unroll
    for (int i = threadIdx.y; i < 32; i += 8) {
        int h = h0 + i, f = f0 + threadIdx.x;
        Ths[(size_t)h * Fp + f] = __float2half_rn(t[threadIdx.x][i]);
    }
}

// ============================================================================
// Output zero + final layer-4 dot + segment scatter-add
// ============================================================================
__global__ void zero_out(float* out, int n) {
    int i = blockIdx.x * blockDim.x + threadIdx.x;
    if (i < n) out[i] = 0.f;
}

__global__ void __launch_bounds__(256)
layer4_reduce(const __half* __restrict__ Hh, const __half* __restrict__ Hl,
              const float* __restrict__ W4, const float* __restrict__ b4,
              const int* __restrict__ sidx, float* __restrict__ out)
{
    __shared__ float w[HIDDEN];
    const int atom = blockIdx.x * 256 + threadIdx.x;
    const int s = atom >> 13;
    w[threadIdx.x] = W4[s * HIDDEN + threadIdx.x];
    __syncthreads();

    const uint4* ph = (const uint4*)(Hh + (size_t)atom * HIDDEN);
    const uint4* pl = (const uint4*)(Hl + (size_t)atom * HIDDEN);
    float e = b4[s];
#pragma unroll 8
    for (int i = 0; i < 32; ++i) {
        uint4 a = ph[i];
        uint4 c = pl[i];
        const uint32_t* ap = &a.x;
        const uint32_t* cp = &c.x;
#pragma unroll
        for (int j = 0; j < 4; ++j) {
            float2 hv = __half22float2(*(__half2*)&ap[j]);
            float2 lv = __half22float2(*(__half2*)&cp[j]);
            int col = i * 8 + j * 2;
            e += (hv.x + lv.x) * w[col];
            e += (hv.y + lv.y) * w[col + 1];
        }
    }
    atomicAdd(out + sidx[atom], e);
}

// ============================================================================
// Host launcher
// ============================================================================
extern "C" void kernel_launch(void* const* d_in, const int* in_sizes, int n_in,
                              void* d_out, int out_size)
{
    int o = 0;
    const float* feat = (const float*)d_in[o++];
    const int* sidx = (const int*)d_in[o++];
    if (o < n_in && in_sizes[o] == 1) o++;  // n_structures scalar, if present
    const float* W1 = (const float*)d_in[o++];
    const float* b1 = (const float*)d_in[o++];
    const float* W2 = (const float*)d_in[o++];
    const float* b2 = (const float*)d_in[o++];
    const float* W3 = (const float*)d_in[o++];
    const float* b3 = (const float*)d_in[o++];
    const float* W4 = (const float*)d_in[o++];
    const float* b4 = (const float*)d_in[o++];

    __half *w1h, *w2h, *w3h, *h1h, *h1l, *h2h, *h2l;
    float* pbuf;
    cudaGetSymbolAddress((void**)&w1h, g_W1h);
    cudaGetSymbolAddress((void**)&w2h, g_W2h);
    cudaGetSymbolAddress((void**)&w3h, g_W3h);
    cudaGetSymbolAddress((void**)&h1h, g_H1h);
    cudaGetSymbolAddress((void**)&h1l, g_H1l);
    cudaGetSymbolAddress((void**)&h2h, g_H2h);
    cudaGetSymbolAddress((void**)&h2l, g_H2l);
    cudaGetSymbolAddress((void**)&pbuf, g_P);

    cudaFuncSetAttribute((const void*)gemm_main<true, true>,
                         cudaFuncAttributeMaxDynamicSharedMemorySize, SMEM_DYN);
    cudaFuncSetAttribute((const void*)gemm_main<false, false>,
                         cudaFuncAttributeMaxDynamicSharedMemorySize, SMEM_DYN);

    // Prep: transpose weights to K-major fp16 (W1 zero-padded to 7616)
    transpose_w<<<dim3(N_FEAT_P / 32, HIDDEN / 32, N_SPECIES), dim3(32, 8)>>>(
        W1, w1h, N_FEAT, N_FEAT_P, HIDDEN);
    transpose_w<<<dim3(HIDDEN / 32, HIDDEN / 32, N_SPECIES), dim3(32, 8)>>>(
        W2, w2h, HIDDEN, HIDDEN, HIDDEN);
    transpose_w<<<dim3(HIDDEN / 32, HIDDEN / 32, N_SPECIES), dim3(32, 8)>>>(
        W3, w3h, HIDDEN, HIDDEN, HIDDEN);

    // Layer 1: fp16 2-term, split-K x4 -> fp32 partials -> combine
    gemm_main<true, true>
        <<<dim3(1, N_ATOMS / MT, NSPLIT), NTHREADS, SMEM_DYN>>>(
        feat, nullptr, nullptr, NCHS, TOTCH,
        w1h, N_FEAT_P, nullptr, nullptr, nullptr, pbuf);
    combine_silu<<<(N_ATOMS * HIDDEN) / (256 * 4), 256>>>(pbuf, b1, h1h, h1l);

    const dim3 grid2(1, N_ATOMS / MT);

    // Layer 2: fp16 2-term (K = 256, 4 chunks)
    gemm_main<false, false><<<grid2, NTHREADS, SMEM_DYN>>>(
        nullptr, h1h, h1l, HIDDEN / KC, HIDDEN / KC,
        w2h, HIDDEN, b2, h2h, h2l, nullptr);

    // Layer 3
    gemm_main<false, false><<<grid2, NTHREADS, SMEM_DYN>>>(
        nullptr, h2h, h2l, HIDDEN / KC, HIDDEN / KC,
        w3h, HIDDEN, b3, h1h, h1l, nullptr);

    // Layer 4 + segment sum
    zero_out<<<(out_size + 255) / 256, 256>>>((float*)d_out, out_size);
    layer4_reduce<<<N_ATOMS / 256, 256>>>(h1h, h1l, W4, b4, sidx, (float*)d_out);
}

// round 14
// speedup vs baseline: 1.2917x; 1.2917x over previous
#include <cuda_runtime.h>
#include <cuda_fp16.h>
#include <cstdint>

// ============================================================================
// Problem constants
// ============================================================================
#define N_ATOMS   32768
#define N_SPECIES 4
#define N_FEAT    7584
#define N_FEAT_P  7616      // padded to multiple of KC
#define HIDDEN    256

#define MT       128        // CTA rows
#define NT       256        // CTA cols (full hidden width)
#define KC       64         // k-chunk per stage
#define NTHREADS 512        // 16 warps, 32x64 warp tiles
#define TOTCH    (N_FEAT_P / KC)   // 119
#define NCHS     30                // split-K chunks/slice (30,30,30,29)
#define NSPLIT   4

// smem: rows of 64 fp16 = 128B data + 16B pad -> conflict-free ldmatrix
#define RST      144
#define APLANE   (128 * RST)           // 18432
#define BPLANE   (256 * RST)           // 36864
#define NSTAGE   3

// ============================================================================
// Device scratch (allocation-free)
// ============================================================================
__device__ __align__(16) __half g_W1h[(size_t)N_SPECIES * HIDDEN * N_FEAT_P];
__device__ __align__(16) __half g_W2h[N_SPECIES * HIDDEN * HIDDEN];
__device__ __align__(16) __half g_W3h[N_SPECIES * HIDDEN * HIDDEN];
__device__ __align__(16) __half g_H1h[(size_t)N_ATOMS * HIDDEN];
__device__ __align__(16) __half g_H1l[(size_t)N_ATOMS * HIDDEN];
__device__ __align__(16) __half g_H2h[(size_t)N_ATOMS * HIDDEN];
__device__ __align__(16) __half g_H2l[(size_t)N_ATOMS * HIDDEN];
__device__ __align__(16) float  g_P[(size_t)NSPLIT * N_ATOMS * HIDDEN];

// ============================================================================
// Baseline-PTX primitives
// ============================================================================
__device__ __forceinline__ void cp16(uint32_t s, const void* g) {
    asm volatile("cp.async.cg.shared.global [%0], [%1], 16;\n" :: "r"(s), "l"(g));
}
__device__ __forceinline__ void cp_commit() {
    asm volatile("cp.async.commit_group;\n" ::: "memory");
}
template<int N> __device__ __forceinline__ void cp_wait() {
    asm volatile("cp.async.wait_group %0;\n" :: "n"(N) : "memory");
}
__device__ __forceinline__ void ldsm4(uint32_t& r0, uint32_t& r1, uint32_t& r2,
                                      uint32_t& r3, uint32_t a) {
    asm volatile("ldmatrix.sync.aligned.m8n8.x4.shared.b16 {%0,%1,%2,%3}, [%4];\n"
                 : "=r"(r0), "=r"(r1), "=r"(r2), "=r"(r3) : "r"(a));
}
__device__ __forceinline__ void mmaf16(float* c, const uint32_t* a, const uint32_t* b) {
    asm volatile(
        "mma.sync.aligned.m16n8k16.row.col.f32.f16.f16.f32 "
        "{%0,%1,%2,%3}, {%4,%5,%6,%7}, {%8,%9}, {%0,%1,%2,%3};\n"
        : "+f"(c[0]), "+f"(c[1]), "+f"(c[2]), "+f"(c[3])
        : "r"(a[0]), "r"(a[1]), "r"(a[2]), "r"(a[3]), "r"(b[0]), "r"(b[1]));
}
__device__ __forceinline__ uint32_t pkh(__half a, __half b) {
    __half2 t; t.x = a; t.y = b;
    return *(uint32_t*)&t;
}

// Fragment set for one k16 step (32x64 warp tile)
struct Frag {
    uint32_t ah[2][4], al[2][4];   // A: 2 m16 tiles (al used only when TERMS==2)
    uint32_t bh[8][2];             // B: 8 n8 tiles, hi plane only
};

// ============================================================================
// Stage loaders (512 threads, KC=64).  Layout per stage:
//   TERMS==1: [A hi][B]            stage = APLANE + BPLANE
//   TERMS==2: [A hi][A lo][B]      stage = 2*APLANE + BPLANE
// ============================================================================
template<int TERMS>
__device__ __forceinline__ void cp_B(uint32_t st, const __half* B0, int ldb, int k0,
                                     int tid) {
    constexpr uint32_t SOFF_B = (TERMS == 1) ? APLANE : 2 * APLANE;
#pragma unroll
    for (int i = 0; i < 4; ++i) {
        int j = tid + i * NTHREADS;
        int n = j >> 3, seg = j & 7;
        cp16(st + SOFF_B + n * RST + seg * 16, B0 + (size_t)n * ldb + k0 + seg * 8);
    }
}
// A hi/lo planes via cp (layers 2/3, TERMS==2)
__device__ __forceinline__ void cp_A2(uint32_t st, const __half* Ah0, const __half* Al0,
                                      int k0, int tid) {
#pragma unroll
    for (int i = 0; i < 2; ++i) {
        int j = tid + i * NTHREADS;
        int m = j >> 3, seg = j & 7;
        cp16(st + m * RST + seg * 16, Ah0 + (size_t)m * HIDDEN + k0 + seg * 8);
        cp16(st + APLANE + m * RST + seg * 16, Al0 + (size_t)m * HIDDEN + k0 + seg * 8);
    }
}
// A fp32 (features): 128 rows x 16 quads = 2048 float4 -> halves of 2/thread
template<int H>
__device__ __forceinline__ void ldg_A_half(float4 av[2], const float* Abase, int k0,
                                           int tid, int Klim) {
#pragma unroll
    for (int i = 0; i < 2; ++i) {
        int j = tid + (H * 2 + i) * NTHREADS;
        int r = j >> 4, q = j & 15;
        int kg = k0 + q * 4;
        if (kg < Klim) av[i] = *(const float4*)(Abase + (size_t)r * N_FEAT + kg);
        else           av[i] = make_float4(0.f, 0.f, 0.f, 0.f);
    }
}
// 1-term: round straight to fp16, single plane
template<int H>
__device__ __forceinline__ void sts_A_half(const float4 av[2], char* sm, uint32_t stOff,
                                           int tid) {
#pragma unroll
    for (int i = 0; i < 2; ++i) {
        int j = tid + (H * 2 + i) * NTHREADS;
        int r = j >> 4, q = j & 15;
        float4 x = av[i];
        uint2 hp;
        hp.x = pkh(__float2half_rn(x.x), __float2half_rn(x.y));
        hp.y = pkh(__float2half_rn(x.z), __float2half_rn(x.w));
        *(uint2*)(sm + stOff + r * RST + q * 8) = hp;
    }
}

// ============================================================================
// Fragment load + MMA
// ============================================================================
template<int TERMS>
__device__ __forceinline__ void ldsm_step(uint32_t st, int ks, Frag& f,
                                          const uint32_t aOff[2], const uint32_t bOff[4]) {
#pragma unroll
    for (int mt = 0; mt < 2; ++mt) {
        ldsm4(f.ah[mt][0], f.ah[mt][1], f.ah[mt][2], f.ah[mt][3], st + aOff[mt] + ks * 32);
        if (TERMS == 2)
            ldsm4(f.al[mt][0], f.al[mt][1], f.al[mt][2], f.al[mt][3],
                  st + aOff[mt] + APLANE + ks * 32);
    }
#pragma unroll
    for (int ng = 0; ng < 4; ++ng)
        ldsm4(f.bh[2 * ng][0], f.bh[2 * ng][1], f.bh[2 * ng + 1][0], f.bh[2 * ng + 1][1],
              st + bOff[ng] + ks * 32);
}
template<int TERMS>
__device__ __forceinline__ void mma_step(float acc[2][8][4], const Frag& f) {
#pragma unroll
    for (int mt = 0; mt < 2; ++mt)
#pragma unroll
        for (int nt = 0; nt < 8; ++nt)
            mmaf16(acc[mt][nt], f.ah[mt], f.bh[nt]);
    if (TERMS == 2) {
#pragma unroll
        for (int mt = 0; mt < 2; ++mt)
#pragma unroll
            for (int nt = 0; nt < 8; ++nt)
                mmaf16(acc[mt][nt], f.al[mt], f.bh[nt]);
    }
}

// ============================================================================
// Main GEMM.  D[m,n] = sum_k A[m,k]*B[n,k]
//   TERMS==1: A fp16 single plane (layer 1).  TERMS==2: A hi/lo (layers 2/3).
// ============================================================================
template<bool AFP32, int TERMS, bool SPLIT>
__global__ void __launch_bounds__(NTHREADS, 1)
gemm_main(const float* __restrict__ Afp,
          const __half* __restrict__ Ahg, const __half* __restrict__ Alg,
          int nchS, int nchTot,
          const __half* __restrict__ Bhg, int ldb,
          const float* __restrict__ bias,
          __half* __restrict__ Oh, __half* __restrict__ Ol,
          float* __restrict__ Pout)
{
    constexpr uint32_t STG = (TERMS == 1) ? (APLANE + BPLANE) : (2 * APLANE + BPLANE);
    constexpr uint32_t SOFF_B = (TERMS == 1) ? APLANE : 2 * APLANE;
    constexpr uint32_t OFF_BIAS = NSTAGE * STG;

    extern __shared__ char sm[];
    const uint32_t sb = (uint32_t)__cvta_generic_to_shared(sm);
    const int tid = threadIdx.x;
    const int row0 = blockIdx.y * MT;
    const int s = row0 >> 13;
    const int z = SPLIT ? blockIdx.z : 0;
    const int kbase = z * nchS * KC;
    const int nch = SPLIT ? min(nchS, nchTot - z * nchS) : nchS;
    const int Klim = AFP32 ? (N_FEAT - kbase) : 0x7fffffff;

    const __half* Bh0 = Bhg + (size_t)s * HIDDEN * ldb + kbase;
    const float* Abase = AFP32 ? (Afp + (size_t)row0 * N_FEAT + kbase) : nullptr;
    const __half* Ah0 = AFP32 ? nullptr : (Ahg + (size_t)row0 * HIDDEN);
    const __half* Al0 = AFP32 ? nullptr : (Alg + (size_t)row0 * HIDDEN);

    float* sbias = (float*)(sm + OFF_BIAS);
    if (!SPLIT && tid < NT) sbias[tid] = bias[s * HIDDEN + tid];

    // ---- prologue: fill stages 0 and 1 ----
    float4 av[2];
    if (AFP32) {
        ldg_A_half<0>(av, Abase, 0, tid, Klim);
        sts_A_half<0>(av, sm, 0, tid);
        ldg_A_half<1>(av, Abase, 0, tid, Klim);
        sts_A_half<1>(av, sm, 0, tid);
    } else {
        cp_A2(sb, Ah0, Al0, 0, tid);
    }
    cp_B<TERMS>(sb, Bh0, ldb, 0, tid);
    cp_commit();
    if (AFP32) {
        ldg_A_half<0>(av, Abase, KC, tid, Klim);
        sts_A_half<0>(av, sm, STG, tid);
        ldg_A_half<1>(av, Abase, KC, tid, Klim);
        sts_A_half<1>(av, sm, STG, tid);
    } else {
        cp_A2(sb + STG, Ah0, Al0, KC, tid);
    }
    cp_B<TERMS>(sb + STG, Bh0, ldb, KC, tid);
    cp_commit();

    // ---- per-warp fragment addressing: 16 warps, 32x64 tiles (4M x 4N) ----
    const int lane = tid & 31, wid = tid >> 5;
    const int m0 = (wid & 3) * 32, n0 = (wid >> 2) * 64;
    const int lr = lane & 15, lcb = (lane >> 4) * 16;
    uint32_t aOff[2], bOff[4];
#pragma unroll
    for (int mt = 0; mt < 2; ++mt)
        aOff[mt] = (uint32_t)(m0 + mt * 16 + lr) * RST + lcb;
    const int brow = (lane & 7) + ((lane & 16) >> 1);
    const int bcb = (lane & 8) * 2;
#pragma unroll
    for (int ng = 0; ng < 4; ++ng)
        bOff[ng] = SOFF_B + (uint32_t)(n0 + ng * 16 + brow) * RST + bcb;

    float acc[2][8][4];
#pragma unroll
    for (int mt = 0; mt < 2; ++mt)
#pragma unroll
        for (int nt = 0; nt < 8; ++nt)
#pragma unroll
            for (int q = 0; q < 4; ++q) acc[mt][nt][q] = 0.f;

    // ---- main loop: 3-stage ring, cp_wait<1>, chores spread over k-steps ----
    Frag f;
    int stc = 0, st2 = 2;
    for (int c = 0; c < nch; ++c) {
        if (c + 1 < nch) { cp_wait<1>(); } else { cp_wait<0>(); }
        __syncthreads();
        const uint32_t cur = sb + (uint32_t)stc * STG;
        const uint32_t nx2 = sb + (uint32_t)st2 * STG;
        const uint32_t nx2off = (uint32_t)st2 * STG;
        const bool pf = (c + 2 < nch);
        const int k2 = (c + 2) * KC;

        // ks0: + ldg half0 of A(c+2)
        ldsm_step<TERMS>(cur, 0, f, aOff, bOff);
        if (AFP32 && pf) ldg_A_half<0>(av, Abase, k2, tid, Klim);
        mma_step<TERMS>(acc, f);

        // ks1: + sts half0 -> stage c+2, cp_B(c+2)
        ldsm_step<TERMS>(cur, 1, f, aOff, bOff);
        if (AFP32 && pf) sts_A_half<0>(av, sm, nx2off, tid);
        if (pf) cp_B<TERMS>(nx2, Bh0, ldb, k2, tid);
        mma_step<TERMS>(acc, f);

        // ks2: + ldg half1, cp_A (layers 2/3), commit
        ldsm_step<TERMS>(cur, 2, f, aOff, bOff);
        if (AFP32 && pf) ldg_A_half<1>(av, Abase, k2, tid, Klim);
        if (pf) {
            if (!AFP32) cp_A2(nx2, Ah0, Al0, k2, tid);
            cp_commit();
        }
        mma_step<TERMS>(acc, f);

        // ks3: + sts half1 -> stage c+2
        ldsm_step<TERMS>(cur, 3, f, aOff, bOff);
        if (AFP32 && pf) sts_A_half<1>(av, sm, nx2off, tid);
        mma_step<TERMS>(acc, f);

        stc = (stc == 2) ? 0 : stc + 1;
        st2 = (st2 == 2) ? 0 : st2 + 1;
    }

    // ---- epilogue ----
    if (SPLIT) {
        float* P = Pout + (size_t)z * N_ATOMS * HIDDEN;
#pragma unroll
        for (int mt = 0; mt < 2; ++mt)
#pragma unroll
            for (int nt = 0; nt < 8; ++nt) {
                const int rg = row0 + m0 + mt * 16 + (lane >> 2);
                const int cg = n0 + nt * 8 + (lane & 3) * 2;
                *(float2*)(P + (size_t)rg * HIDDEN + cg) =
                    make_float2(acc[mt][nt][0], acc[mt][nt][1]);
                *(float2*)(P + (size_t)(rg + 8) * HIDDEN + cg) =
                    make_float2(acc[mt][nt][2], acc[mt][nt][3]);
            }
    } else {
#pragma unroll
        for (int mt = 0; mt < 2; ++mt)
#pragma unroll
            for (int nt = 0; nt < 8; ++nt) {
                const int rg = row0 + m0 + mt * 16 + (lane >> 2);
                const int cg = n0 + nt * 8 + (lane & 3) * 2;
                const float b0 = sbias[cg], b1 = sbias[cg + 1];
                float v[4];
                v[0] = acc[mt][nt][0] + b0; v[1] = acc[mt][nt][1] + b1;
                v[2] = acc[mt][nt][2] + b0; v[3] = acc[mt][nt][3] + b1;
#pragma unroll
                for (int q = 0; q < 4; ++q) v[q] = v[q] / (1.f + __expf(-v[q]));
                __half h0 = __float2half_rn(v[0]), h1 = __float2half_rn(v[1]);
                __half h2 = __float2half_rn(v[2]), h3 = __float2half_rn(v[3]);
                uint32_t hi0 = pkh(h0, h1), hi1 = pkh(h2, h3);
                uint32_t lo0 = pkh(__float2half_rn(v[0] - __half2float(h0)),
                                   __float2half_rn(v[1] - __half2float(h1)));
                uint32_t lo1 = pkh(__float2half_rn(v[2] - __half2float(h2)),
                                   __float2half_rn(v[3] - __half2float(h3)));
                *(uint32_t*)(Oh + (size_t)rg * HIDDEN + cg) = hi0;
                *(uint32_t*)(Ol + (size_t)rg * HIDDEN + cg) = lo0;
                *(uint32_t*)(Oh + (size_t)(rg + 8) * HIDDEN + cg) = hi1;
                *(uint32_t*)(Ol + (size_t)(rg + 8) * HIDDEN + cg) = lo1;
            }
    }
}

// ============================================================================
// Split-K combine: sum 4 partials + bias -> silu -> fp16 hi/lo planes
// ============================================================================
__global__ void __launch_bounds__(256)
combine_silu(const float* __restrict__ P, const float* __restrict__ bias,
             __half* __restrict__ Oh, __half* __restrict__ Ol)
{
    const size_t i4 = ((size_t)blockIdx.x * 256 + threadIdx.x) * 4;
    const int row = (int)(i4 >> 8);
    const int col = (int)(i4 & 255);
    const int s = row >> 13;
    float4 a0 = *(const float4*)(P + i4);
    float4 a1 = *(const float4*)(P + (size_t)N_ATOMS * HIDDEN + i4);
    float4 a2 = *(const float4*)(P + (size_t)2 * N_ATOMS * HIDDEN + i4);
    float4 a3 = *(const float4*)(P + (size_t)3 * N_ATOMS * HIDDEN + i4);
    const float* bp = bias + s * HIDDEN + col;
    float v[4] = {(a0.x + a1.x) + (a2.x + a3.x) + bp[0],
                  (a0.y + a1.y) + (a2.y + a3.y) + bp[1],
                  (a0.z + a1.z) + (a2.z + a3.z) + bp[2],
                  (a0.w + a1.w) + (a2.w + a3.w) + bp[3]};
#pragma unroll
    for (int q = 0; q < 4; ++q) v[q] = v[q] / (1.f + __expf(-v[q]));
    __half h0 = __float2half_rn(v[0]), h1 = __float2half_rn(v[1]);
    __half h2 = __float2half_rn(v[2]), h3 = __float2half_rn(v[3]);
    uint2 hp, lp;
    hp.x = pkh(h0, h1); hp.y = pkh(h2, h3);
    lp.x = pkh(__float2half_rn(v[0] - __half2float(h0)),
               __float2half_rn(v[1] - __half2float(h1)));
    lp.y = pkh(__float2half_rn(v[2] - __half2float(h2)),
               __float2half_rn(v[3] - __half2float(h3)));
    *(uint2*)(Oh + i4) = hp;
    *(uint2*)(Ol + i4) = lp;
}

// ============================================================================
// Weight transpose to K-major fp16 (zero-padded to Fp):  W[s][f][h] -> T[s][h][fp]
// ============================================================================
__global__ void transpose_w(const float* __restrict__ W, __half* __restrict__ Th,
                            int F, int Fp, int H)
{
    __shared__ float t[32][33];
    const int s = blockIdx.z;
    const int f0 = blockIdx.x * 32, h0 = blockIdx.y * 32;
    const float* Ws = W + (size_t)s * F * H;
#pragma unroll
    for (int i = threadIdx.y; i < 32; i += 8) {
        int f = f0 + i, h = h0 + threadIdx.x;
        t[i][threadIdx.x] = (f < F) ? Ws[(size_t)f * H + h] : 0.f;
    }
    __syncthreads();
    __half* Ths = Th + (size_t)s * H * Fp;
#pragma unroll
    for (int i = threadIdx.y; i < 32; i += 8) {
        int h = h0 + i, f = f0 + threadIdx.x;
        Ths[(size_t)h * Fp + f] = __float2half_rn(t[threadIdx.x][i]);
    }
}

// ============================================================================
// Output zero + final layer-4 dot + segment scatter-add
// ============================================================================
__global__ void zero_out(float* out, int n) {
    int i = blockIdx.x * blockDim.x + threadIdx.x;
    if (i < n) out[i] = 0.f;
}

__global__ void __launch_bounds__(256)
layer4_reduce(const __half* __restrict__ Hh, const __half* __restrict__ Hl,
              const float* __restrict__ W4, const float* __restrict__ b4,
              const int* __restrict__ sidx, float* __restrict__ out)
{
    __shared__ float w[HIDDEN];
    const int atom = blockIdx.x * 256 + threadIdx.x;
    const int s = atom >> 13;
    w[threadIdx.x] = W4[s * HIDDEN + threadIdx.x];
    __syncthreads();

    const uint4* ph = (const uint4*)(Hh + (size_t)atom * HIDDEN);
    const uint4* pl = (const uint4*)(Hl + (size_t)atom * HIDDEN);
    float e = b4[s];
#pragma unroll 8
    for (int i = 0; i < 32; ++i) {
        uint4 a = ph[i];
        uint4 c = pl[i];
        const uint32_t* ap = &a.x;
        const uint32_t* cp = &c.x;
#pragma unroll
        for (int j = 0; j < 4; ++j) {
            float2 hv = __half22float2(*(__half2*)&ap[j]);
            float2 lv = __half22float2(*(__half2*)&cp[j]);
            int col = i * 8 + j * 2;
            e += (hv.x + lv.x) * w[col];
            e += (hv.y + lv.y) * w[col + 1];
        }
    }
    atomicAdd(out + sidx[atom], e);
}

// ============================================================================
// Host launcher
// ============================================================================
extern "C" void kernel_launch(void* const* d_in, const int* in_sizes, int n_in,
                              void* d_out, int out_size)
{
    int o = 0;
    const float* feat = (const float*)d_in[o++];
    const int* sidx = (const int*)d_in[o++];
    if (o < n_in && in_sizes[o] == 1) o++;  // n_structures scalar, if present
    const float* W1 = (const float*)d_in[o++];
    const float* b1 = (const float*)d_in[o++];
    const float* W2 = (const float*)d_in[o++];
    const float* b2 = (const float*)d_in[o++];
    const float* W3 = (const float*)d_in[o++];
    const float* b3 = (const float*)d_in[o++];
    const float* W4 = (const float*)d_in[o++];
    const float* b4 = (const float*)d_in[o++];

    __half *w1h, *w2h, *w3h, *h1h, *h1l, *h2h, *h2l;
    float* pbuf;
    cudaGetSymbolAddress((void**)&w1h, g_W1h);
    cudaGetSymbolAddress((void**)&w2h, g_W2h);
    cudaGetSymbolAddress((void**)&w3h, g_W3h);
    cudaGetSymbolAddress((void**)&h1h, g_H1h);
    cudaGetSymbolAddress((void**)&h1l, g_H1l);
    cudaGetSymbolAddress((void**)&h2h, g_H2h);
    cudaGetSymbolAddress((void**)&h2l, g_H2l);
    cudaGetSymbolAddress((void**)&pbuf, g_P);

    const int SMEM1 = NSTAGE * (APLANE + BPLANE) + 1024;      // 166912 (1-term)
    const int SMEM2 = NSTAGE * (2 * APLANE + BPLANE) + 1024;  // 222208 (2-term)
    cudaFuncSetAttribute((const void*)gemm_main<true, 1, true>,
                         cudaFuncAttributeMaxDynamicSharedMemorySize, SMEM1);
    cudaFuncSetAttribute((const void*)gemm_main<false, 2, false>,
                         cudaFuncAttributeMaxDynamicSharedMemorySize, SMEM2);

    // Prep: transpose weights to K-major fp16 (W1 zero-padded to 7616)
    transpose_w<<<dim3(N_FEAT_P / 32, HIDDEN / 32, N_SPECIES), dim3(32, 8)>>>(
        W1, w1h, N_FEAT, N_FEAT_P, HIDDEN);
    transpose_w<<<dim3(HIDDEN / 32, HIDDEN / 32, N_SPECIES), dim3(32, 8)>>>(
        W2, w2h, HIDDEN, HIDDEN, HIDDEN);
    transpose_w<<<dim3(HIDDEN / 32, HIDDEN / 32, N_SPECIES), dim3(32, 8)>>>(
        W3, w3h, HIDDEN, HIDDEN, HIDDEN);

    // Layer 1: fp16 1-term, split-K x4 -> fp32 partials -> combine
    gemm_main<true, 1, true>
        <<<dim3(1, N_ATOMS / MT, NSPLIT), NTHREADS, SMEM1>>>(
        feat, nullptr, nullptr, NCHS, TOTCH,
        w1h, N_FEAT_P, nullptr, nullptr, nullptr, pbuf);
    combine_silu<<<(N_ATOMS * HIDDEN) / (256 * 4), 256>>>(pbuf, b1, h1h, h1l);

    const dim3 grid2(1, N_ATOMS / MT);

    // Layer 2: fp16 2-term (K = 256, 4 chunks)
    gemm_main<false, 2, false><<<grid2, NTHREADS, SMEM2>>>(
        nullptr, h1h, h1l, HIDDEN / KC, HIDDEN / KC,
        w2h, HIDDEN, b2, h2h, h2l, nullptr);

    // Layer 3
    gemm_main<false, 2, false><<<grid2, NTHREADS, SMEM2>>>(
        nullptr, h2h, h2l, HIDDEN / KC, HIDDEN / KC,
        w3h, HIDDEN, b3, h1h, h1l, nullptr);

    // Layer 4 + segment sum
    zero_out<<<(out_size + 255) / 256, 256>>>((float*)d_out, out_size);
    layer4_reduce<<<N_ATOMS / 256, 256>>>(h1h, h1l, W4, b4, sidx, (float*)d_out);
}